// round 7
// baseline (speedup 1.0000x reference)
#include <cuda_runtime.h>
#include <cuda_bf16.h>
#include <math.h>

// Problem constants: N=50000 nodes, E=800000 edges, F=64, HID=64, OUT=32
#define MAXN 50176      // padded to 49*1024 (divisible by 4)
#define MAXE 800008     // +8 pad: gather prefetches one past segment end

// ---------- device scratch (no allocations allowed) ----------
__device__ __align__(16) float g_deg[MAXN];
__device__ __align__(16) float g_dinv[MAXN];
__device__ __align__(16) int   g_count[MAXN];
__device__ __align__(16) int   g_cursor[MAXN];
__device__ __align__(16) int   g_offs[MAXN];
__device__ __align__(16) int   g_bsum[64];
__device__ __align__(16) int   g_bpref[64];
__device__ __align__(16) int2  g_pair[MAXE];   // (src, bitcast(coef)) interleaved
__device__ int g_is64;   // 1 if edge_index is int64, 0 if int32

__device__ __forceinline__ int load_idx(const void* ei, int pos) {
    if (g_is64) return (int)((const long long*)ei)[pos];
    return ((const int*)ei)[pos];
}
__device__ __forceinline__ int clampi(int v, int n) {
    return ((unsigned)v < (unsigned)n) ? v : 0;
}

// ---------- K1: zero per-node scratch (vectorized) + dtype detect ----------
__global__ void k_init(const int* __restrict__ ei32) {
    int i = blockIdx.x * blockDim.x + threadIdx.x;   // int4 index
    if (i < MAXN / 4) {
        int4 z = make_int4(0, 0, 0, 0);
        reinterpret_cast<int4*>(g_deg)[i] = z;
        reinterpret_cast<int4*>(g_count)[i] = z;
        reinterpret_cast<int4*>(g_cursor)[i] = z;
    }
    if (blockIdx.x == 0) {
        if (threadIdx.x < 64) g_bpref[threadIdx.x] = 0;
        __shared__ int any;
        if (threadIdx.x == 0) any = 0;
        __syncthreads();
        // int64 with small nonneg values -> every odd 32-bit word is 0
        if (threadIdx.x < 128 && ei32[2 * threadIdx.x + 1] != 0) atomicOr(&any, 1);
        __syncthreads();
        if (threadIdx.x == 0) g_is64 = (any == 0) ? 1 : 0;
    }
}

// ---------- K2: degree (by src) + per-dst edge count ----------
__global__ void k_edge1(const void* __restrict__ ei, const float* __restrict__ ew, int e, int n) {
    int i = blockIdx.x * blockDim.x + threadIdx.x;
    if (i < e) {
        int s = clampi(load_idx(ei, i), n);
        int d = clampi(load_idx(ei, e + i), n);
        atomicAdd(&g_deg[s], ew[i]);
        atomicAdd(&g_count[d], 1);
    }
}

// ---------- K3: dinv + block-local exclusive scan + cross-block prefix (atomics) ----------
__global__ void k_scan_dinv(int n, int nb) {
    __shared__ int sh[1024];
    __shared__ int s_total;
    int t = threadIdx.x;
    int i = blockIdx.x * 1024 + t;
    if (i < n) {
        float dg = g_deg[i];
        g_dinv[i] = (dg > 0.f) ? rsqrtf(dg) : 0.f;
    }
    int v = (i < n) ? g_count[i] : 0;
    sh[t] = v;
    __syncthreads();
    for (int d = 1; d < 1024; d <<= 1) {
        int add = (t >= d) ? sh[t - d] : 0;
        __syncthreads();
        sh[t] += add;
        __syncthreads();
    }
    int incl = sh[t];
    if (i < n) g_offs[i] = incl - v;
    if (t == 1023) s_total = incl;
    __syncthreads();
    // propagate this block's total to all later blocks
    int b2 = blockIdx.x + 1 + t;
    if (t < 64 && b2 < nb) atomicAdd(&g_bpref[b2], s_total);
}

// ---------- K4: bucket fill (CSR) with normalized coefficient ----------
__global__ void k_edge2(const void* __restrict__ ei, const float* __restrict__ ew, int e, int n) {
    int i = blockIdx.x * blockDim.x + threadIdx.x;
    if (i < e) {
        int s = clampi(load_idx(ei, i), n);
        int d = clampi(load_idx(ei, e + i), n);
        int pos = g_offs[d] + g_bpref[d >> 10] + atomicAdd(&g_cursor[d], 1);
        pos = clampi(pos, e);
        float c = -g_dinv[s] * ew[i] * g_dinv[d];
        g_pair[pos] = make_int2(s, __float_as_int(c));
    }
}

// ---------- K5: gather + [x|px]@Wzh -> gate -> @Wlin -> L2-normalize ----------
// Block: 256 threads (8 warps), TM=32 nodes; warp w gathers dsts w*4..w*4+3.
#define TM 32
__global__ __launch_bounds__(256, 2) void k_fused(
    const float* __restrict__ x,
    const float* __restrict__ Wxz0, const float* __restrict__ Wxz1,
    const float* __restrict__ bxz,  const float* __restrict__ bhz,
    const float* __restrict__ Wxh0, const float* __restrict__ Wxh1,
    const float* __restrict__ bxh,  const float* __restrict__ bhh,
    const float* __restrict__ Wlin, const float* __restrict__ blin,
    float* __restrict__ out, int n)
{
    extern __shared__ __align__(16) float sh[];
    float* sW   = sh;                 // 128*128 = 16384
    float* sWl  = sW + 16384;         // 64*32   = 2048
    float* sB   = sWl + 2048;         // 128
    float* sBl  = sB + 128;           // 32
    float* sIN  = sBl + 32;           // 32*128  = 4096
    float* sU   = sIN + 4096;         // 32*64   = 2048
    // total 24736 floats = 98944 bytes

    int tid = threadIdx.x;
    int node0 = blockIdx.x * TM;

    // weights/biases -> smem
    for (int idx = tid; idx < 16384; idx += 256) {
        int k = idx >> 7, o = idx & 127;
        float v;
        if (k < 64) v = (o < 64) ? Wxz0[k * 64 + o] : Wxh0[k * 64 + (o - 64)];
        else        v = (o < 64) ? Wxz1[(k - 64) * 64 + o] : Wxh1[(k - 64) * 64 + (o - 64)];
        sW[idx] = v;
    }
    for (int idx = tid; idx < 2048; idx += 256) sWl[idx] = Wlin[idx];
    if (tid < 128) sB[tid] = (tid < 64) ? (bxz[tid] + bhz[tid]) : (bxh[tid - 64] + bhh[tid - 64]);
    if (tid < 32) sBl[tid] = blin[tid];

    // x tile -> sIN cols 0..63 (float4)
    for (int idx = tid; idx < TM * 16; idx += 256) {
        int r = idx >> 4, c4 = idx & 15;
        int node = node0 + r;
        float4 v = make_float4(0.f, 0.f, 0.f, 0.f);
        if (node < n) v = reinterpret_cast<const float4*>(x)[(size_t)node * 16 + c4];
        reinterpret_cast<float4*>(&sIN[r * 128])[c4] = v;
    }

    // gather: warp w computes px for dsts node0 + w*4 + {0..3} -> sIN cols 64..127
    {
        int w = tid >> 5, lane = tid & 31;
#pragma unroll
        for (int q = 0; q < 4; q++) {
            int r = w * 4 + q;
            int dst = node0 + r;
            float a0 = 0.f, a1 = 0.f;
            if (dst < n) {
                int start = g_offs[dst] + g_bpref[dst >> 10];
                int m = g_count[dst];
                if (m > 0) {
                    int2 sc = __ldg(&g_pair[start]);
                    for (int j = 0; j < m; j++) {
                        int2 nxt = __ldg(&g_pair[start + j + 1]);  // MAXE pad
                        const float* xr = x + (size_t)sc.x * 64;
                        float c = __int_as_float(sc.y);
                        a0 = fmaf(c, __ldg(&xr[lane]), a0);
                        a1 = fmaf(c, __ldg(&xr[lane + 32]), a1);
                        sc = nxt;
                    }
                }
            }
            sIN[r * 128 + 64 + lane] = a0;
            sIN[r * 128 + 96 + lane] = a1;
        }
    }
    __syncthreads();

    // stage A GEMM: 32 nodes x 128 outputs, K=128
    int og = tid & 31;
    int ng = tid >> 5;
    int obase = og * 4;
    float acc[4][4];
#pragma unroll
    for (int i = 0; i < 4; i++)
#pragma unroll
        for (int j = 0; j < 4; j++) acc[i][j] = sB[obase + j];

#pragma unroll 4
    for (int k = 0; k < 128; k++) {
        float4 w = *reinterpret_cast<const float4*>(&sW[k * 128 + obase]);
#pragma unroll
        for (int i = 0; i < 4; i++) {
            float in = sIN[(ng + i * 8) * 128 + k];
            acc[i][0] = fmaf(in, w.x, acc[i][0]);
            acc[i][1] = fmaf(in, w.y, acc[i][1]);
            acc[i][2] = fmaf(in, w.z, acc[i][2]);
            acc[i][3] = fmaf(in, w.w, acc[i][3]);
        }
    }
    __syncthreads();
#pragma unroll
    for (int i = 0; i < 4; i++) {
        int r = ng + i * 8;
#pragma unroll
        for (int j = 0; j < 4; j++) sIN[r * 128 + obase + j] = acc[i][j];
    }
    __syncthreads();

    // gate: U = (1 - sigmoid(z)) * tanh(h)
    for (int idx = tid; idx < TM * 64; idx += 256) {
        int r = idx >> 6, j = idx & 63;
        float zp = sIN[r * 128 + j];
        float hp = sIN[r * 128 + 64 + j];
        float z = 1.f / (1.f + __expf(-zp));
        sU[idx] = (1.f - z) * tanhf(hp);
    }
    __syncthreads();

    // stage B: U(32x64) @ Wlin(64x32) + blin, then row-normalize
    int node = tid >> 3;
    int og2 = tid & 7;
    int ob = og2 * 4;
    float a0 = sBl[ob], a1 = sBl[ob + 1], a2 = sBl[ob + 2], a3 = sBl[ob + 3];
#pragma unroll 8
    for (int k = 0; k < 64; k++) {
        float u = sU[node * 64 + k];
        float4 w = *reinterpret_cast<const float4*>(&sWl[k * 32 + ob]);
        a0 = fmaf(u, w.x, a0);
        a1 = fmaf(u, w.y, a1);
        a2 = fmaf(u, w.z, a2);
        a3 = fmaf(u, w.w, a3);
    }
    float ss = a0 * a0 + a1 * a1 + a2 * a2 + a3 * a3;
    ss += __shfl_xor_sync(0xffffffffu, ss, 1);
    ss += __shfl_xor_sync(0xffffffffu, ss, 2);
    ss += __shfl_xor_sync(0xffffffffu, ss, 4);
    float scale = 1.f / fmaxf(sqrtf(ss), 1e-12f);
    int gnode = node0 + node;
    if (gnode < n) {
        float4 o4 = make_float4(a0 * scale, a1 * scale, a2 * scale, a3 * scale);
        reinterpret_cast<float4*>(out)[(size_t)gnode * 8 + og2] = o4;
    }
}

extern "C" void kernel_launch(void* const* d_in, const int* in_sizes, int n_in,
                              void* d_out, int out_size) {
    const float* x    = (const float*)d_in[0];
    const void*  ei   = d_in[1];
    const float* ew   = (const float*)d_in[2];
    const float* Wxz0 = (const float*)d_in[3];
    const float* Wxz1 = (const float*)d_in[4];
    const float* bxz  = (const float*)d_in[5];
    const float* bhz  = (const float*)d_in[8];
    const float* Wxh0 = (const float*)d_in[15];
    const float* Wxh1 = (const float*)d_in[16];
    const float* bxh  = (const float*)d_in[17];
    const float* bhh  = (const float*)d_in[20];
    const float* Wlin = (const float*)d_in[21];
    const float* blin = (const float*)d_in[22];
    float* out = (float*)d_out;

    int n = in_sizes[0] / 64;   // 50000
    int e = in_sizes[2];        // 800000

    static int s_attr_done = 0;
    if (!s_attr_done) {
        cudaFuncSetAttribute(k_fused, cudaFuncAttributeMaxDynamicSharedMemorySize, 98944);
        s_attr_done = 1;
    }

    int nbE = (e + 255) / 256;
    int nbScan = (n + 1023) / 1024;

    k_init<<<(MAXN / 4 + 255) / 256, 256>>>((const int*)ei);   // #1
    k_edge1<<<nbE, 256>>>(ei, ew, e, n);                       // #2
    k_scan_dinv<<<nbScan, 1024>>>(n, nbScan);                  // #3
    k_edge2<<<nbE, 256>>>(ei, ew, e, n);                       // #4
    k_fused<<<(n + TM - 1) / TM, 256, 98944>>>(                // #5
        x, Wxz0, Wxz1, bxz, bhz, Wxh0, Wxh1, bxh, bhh, Wlin, blin, out, n);
}

// round 8
// speedup vs baseline: 1.0573x; 1.0573x over previous
#include <cuda_runtime.h>
#include <cuda_bf16.h>
#include <math.h>

// Problem constants: N=50000 nodes, E=800000 edges, F=64, HID=64, OUT=32
#define MAXN 50176      // 49*1024, divisible by 4
#define MAXE 800008     // +8 pad: prop prefetches one past segment end
#define NBZ 49          // zero/scan blocks (1024 elems each)

// ---------- device scratch (no allocations allowed) ----------
__device__ __align__(16) float g_deg[MAXN];
__device__ __align__(16) float g_dinv[MAXN];
__device__ __align__(16) int   g_count[MAXN];
__device__ __align__(16) int   g_cursor[MAXN];
__device__ __align__(16) int   g_offs[MAXN];
__device__ __align__(16) int   g_bpref[64];
__device__ __align__(16) int2  g_pair[MAXE];   // (src, bitcast(coef))
__device__ __align__(16) float g_px[MAXN * 64];
__device__ int g_is64;     // 1 if edge_index is int64, 0 if int32
__device__ int g_done_a;   // zero-phase completion counter (reset by k_fused)
__device__ int g_done_b;   // scan-phase completion counter (reset by k_fused)

__device__ __forceinline__ int load_idx(const void* ei, int pos) {
    if (g_is64) return (int)((const long long*)ei)[pos];
    return ((const int*)ei)[pos];
}
__device__ __forceinline__ int clampi(int v, int n) {
    return ((unsigned)v < (unsigned)n) ? v : 0;
}

// ---------- A: zero + dtype detect (blocks 0..48) | edge1 (blocks 49..) ----------
__global__ void k_zero_edge1(const void* __restrict__ ei, const float* __restrict__ ew,
                             int e, int n) {
    int bid = blockIdx.x, tid = threadIdx.x;
    if (bid < NBZ) {
        int i = bid * 256 + tid;          // int4 index, covers 256*4=1024 elems/block
        int4 z = make_int4(0, 0, 0, 0);
        reinterpret_cast<int4*>(g_deg)[i] = z;
        reinterpret_cast<int4*>(g_count)[i] = z;
        reinterpret_cast<int4*>(g_cursor)[i] = z;
        if (bid == 0) {
            if (tid < 64) g_bpref[tid] = 0;
            __shared__ int any;
            if (tid == 0) any = 0;
            __syncthreads();
            // int64 small nonneg values -> every odd 32-bit word is 0
            if (tid < 128 && ((const int*)ei)[2 * tid + 1] != 0) atomicOr(&any, 1);
            __syncthreads();
            if (tid == 0) g_is64 = (any == 0) ? 1 : 0;
        }
        __syncthreads();
        __threadfence();
        if (tid == 0) atomicAdd(&g_done_a, 1);
    } else {
        if (tid == 0) { while (atomicAdd(&g_done_a, 0) < NBZ) {} }
        __syncthreads();
        __threadfence();
        int i = (bid - NBZ) * 256 + tid;
        if (i < e) {
            int s = clampi(load_idx(ei, i), n);
            int d = clampi(load_idx(ei, e + i), n);
            atomicAdd(&g_deg[s], ew[i]);
            atomicAdd(&g_count[d], 1);
        }
    }
}

// ---------- B: dinv + scan (blocks 0..48) | edge2 bucket fill (blocks 49..) ----------
__global__ void k_scan_edge2(const void* __restrict__ ei, const float* __restrict__ ew,
                             int e, int n) {
    int bid = blockIdx.x, tid = threadIdx.x;
    if (bid < NBZ) {
        __shared__ int sh[256];
        __shared__ int s_total;
        int base = bid * 1024 + tid * 4;
        int4 c4 = reinterpret_cast<const int4*>(g_count)[bid * 256 + tid];
        float4 d4 = reinterpret_cast<const float4*>(g_deg)[bid * 256 + tid];
        float4 dv;
        dv.x = (d4.x > 0.f) ? rsqrtf(d4.x) : 0.f;
        dv.y = (d4.y > 0.f) ? rsqrtf(d4.y) : 0.f;
        dv.z = (d4.z > 0.f) ? rsqrtf(d4.z) : 0.f;
        dv.w = (d4.w > 0.f) ? rsqrtf(d4.w) : 0.f;
        reinterpret_cast<float4*>(g_dinv)[bid * 256 + tid] = dv;
        int tsum = c4.x + c4.y + c4.z + c4.w;
        sh[tid] = tsum;
        __syncthreads();
        for (int d = 1; d < 256; d <<= 1) {
            int add = (tid >= d) ? sh[tid - d] : 0;
            __syncthreads();
            sh[tid] += add;
            __syncthreads();
        }
        int excl = sh[tid] - tsum;   // exclusive prefix for this thread's 4 elems
        int4 o4;
        o4.x = excl;
        o4.y = excl + c4.x;
        o4.z = excl + c4.x + c4.y;
        o4.w = excl + c4.x + c4.y + c4.z;
        reinterpret_cast<int4*>(g_offs)[bid * 256 + tid] = o4;
        (void)base;
        if (tid == 255) s_total = sh[255];
        __syncthreads();
        int b2 = bid + 1 + tid;
        if (tid < 64 && b2 < NBZ) atomicAdd(&g_bpref[b2], s_total);
        __threadfence();
        __syncthreads();
        if (tid == 0) atomicAdd(&g_done_b, 1);
    } else {
        if (tid == 0) { while (atomicAdd(&g_done_b, 0) < NBZ) {} }
        __syncthreads();
        __threadfence();
        int i = (bid - NBZ) * 256 + tid;
        if (i < e) {
            int s = clampi(load_idx(ei, i), n);
            int d = clampi(load_idx(ei, e + i), n);
            int pos = g_offs[d] + g_bpref[d >> 10] + atomicAdd(&g_cursor[d], 1);
            pos = clampi(pos, e);
            float c = -g_dinv[s] * ew[i] * g_dinv[d];
            g_pair[pos] = make_int2(s, __float_as_int(c));
        }
    }
}

// ---------- K3: propagation px[dst] = sum coef * x[src], one warp per dst ----------
__global__ void k_prop(const float* __restrict__ x, int n) {
    int gw = (blockIdx.x * blockDim.x + threadIdx.x) >> 5;
    int lane = threadIdx.x & 31;
    if (gw >= n) return;
    int start = g_offs[gw] + g_bpref[gw >> 10];
    int m = g_count[gw];
    float a0 = 0.f, a1 = 0.f;
    if (m > 0) {
        int2 sc = __ldg(&g_pair[start]);
        for (int j = 0; j < m; j++) {
            int2 nxt = __ldg(&g_pair[start + j + 1]);  // MAXE pad
            const float* xr = x + (size_t)sc.x * 64;
            float c = __int_as_float(sc.y);
            a0 = fmaf(c, __ldg(&xr[lane]), a0);
            a1 = fmaf(c, __ldg(&xr[lane + 32]), a1);
            sc = nxt;
        }
    }
    g_px[(size_t)gw * 64 + lane] = a0;
    g_px[(size_t)gw * 64 + 32 + lane] = a1;
}

// ---------- K4: fused [x|px]@Wzh -> gate -> @Wlin -> L2-normalize ----------
#define TM 32
__global__ __launch_bounds__(256, 2) void k_fused(
    const float* __restrict__ x,
    const float* __restrict__ Wxz0, const float* __restrict__ Wxz1,
    const float* __restrict__ bxz,  const float* __restrict__ bhz,
    const float* __restrict__ Wxh0, const float* __restrict__ Wxh1,
    const float* __restrict__ bxh,  const float* __restrict__ bhh,
    const float* __restrict__ Wlin, const float* __restrict__ blin,
    float* __restrict__ out, int n)
{
    extern __shared__ __align__(16) float sh[];
    float* sW   = sh;                 // 128*128 = 16384
    float* sWl  = sW + 16384;         // 64*32   = 2048
    float* sB   = sWl + 2048;         // 128
    float* sBl  = sB + 128;           // 32
    float* sIN  = sBl + 32;           // 32*128  = 4096
    float* sU   = sIN + 4096;         // 32*64   = 2048
    // total 24736 floats = 98944 bytes

    int tid = threadIdx.x;
    // reset software-barrier counters for the next graph replay
    if (blockIdx.x == 0 && tid == 0) { g_done_a = 0; g_done_b = 0; }

    for (int idx = tid; idx < 16384; idx += 256) {
        int k = idx >> 7, o = idx & 127;
        float v;
        if (k < 64) v = (o < 64) ? Wxz0[k * 64 + o] : Wxh0[k * 64 + (o - 64)];
        else        v = (o < 64) ? Wxz1[(k - 64) * 64 + o] : Wxh1[(k - 64) * 64 + (o - 64)];
        sW[idx] = v;
    }
    for (int idx = tid; idx < 2048; idx += 256) sWl[idx] = Wlin[idx];
    if (tid < 128) sB[tid] = (tid < 64) ? (bxz[tid] + bhz[tid]) : (bxh[tid - 64] + bhh[tid - 64]);
    if (tid < 32) sBl[tid] = blin[tid];

    int node0 = blockIdx.x * TM;

    for (int idx = tid; idx < TM * 32; idx += 256) {
        int r = idx >> 5, c4 = idx & 31;
        int node = node0 + r;
        float4 v = make_float4(0.f, 0.f, 0.f, 0.f);
        if (node < n) {
            if (c4 < 16) v = reinterpret_cast<const float4*>(x)[(size_t)node * 16 + c4];
            else         v = reinterpret_cast<const float4*>(g_px)[(size_t)node * 16 + (c4 - 16)];
        }
        reinterpret_cast<float4*>(sIN)[idx] = v;
    }
    __syncthreads();

    int og = tid & 31;
    int ng = tid >> 5;
    int obase = og * 4;
    float acc[4][4];
#pragma unroll
    for (int i = 0; i < 4; i++)
#pragma unroll
        for (int j = 0; j < 4; j++) acc[i][j] = sB[obase + j];

#pragma unroll 4
    for (int k = 0; k < 128; k++) {
        float4 w = *reinterpret_cast<const float4*>(&sW[k * 128 + obase]);
#pragma unroll
        for (int i = 0; i < 4; i++) {
            float in = sIN[(ng + i * 8) * 128 + k];
            acc[i][0] = fmaf(in, w.x, acc[i][0]);
            acc[i][1] = fmaf(in, w.y, acc[i][1]);
            acc[i][2] = fmaf(in, w.z, acc[i][2]);
            acc[i][3] = fmaf(in, w.w, acc[i][3]);
        }
    }
    __syncthreads();
#pragma unroll
    for (int i = 0; i < 4; i++) {
        int r = ng + i * 8;
#pragma unroll
        for (int j = 0; j < 4; j++) sIN[r * 128 + obase + j] = acc[i][j];
    }
    __syncthreads();

    for (int idx = tid; idx < TM * 64; idx += 256) {
        int r = idx >> 6, j = idx & 63;
        float zp = sIN[r * 128 + j];
        float hp = sIN[r * 128 + 64 + j];
        float z = 1.f / (1.f + __expf(-zp));
        sU[idx] = (1.f - z) * tanhf(hp);
    }
    __syncthreads();

    int node = tid >> 3;
    int og2 = tid & 7;
    int ob = og2 * 4;
    float a0 = sBl[ob], a1 = sBl[ob + 1], a2 = sBl[ob + 2], a3 = sBl[ob + 3];
#pragma unroll 8
    for (int k = 0; k < 64; k++) {
        float u = sU[node * 64 + k];
        float4 w = *reinterpret_cast<const float4*>(&sWl[k * 32 + ob]);
        a0 = fmaf(u, w.x, a0);
        a1 = fmaf(u, w.y, a1);
        a2 = fmaf(u, w.z, a2);
        a3 = fmaf(u, w.w, a3);
    }
    float ss = a0 * a0 + a1 * a1 + a2 * a2 + a3 * a3;
    ss += __shfl_xor_sync(0xffffffffu, ss, 1);
    ss += __shfl_xor_sync(0xffffffffu, ss, 2);
    ss += __shfl_xor_sync(0xffffffffu, ss, 4);
    float scale = 1.f / fmaxf(sqrtf(ss), 1e-12f);
    int gnode = node0 + node;
    if (gnode < n) {
        float4 o4 = make_float4(a0 * scale, a1 * scale, a2 * scale, a3 * scale);
        reinterpret_cast<float4*>(out)[(size_t)gnode * 8 + og2] = o4;
    }
}

extern "C" void kernel_launch(void* const* d_in, const int* in_sizes, int n_in,
                              void* d_out, int out_size) {
    const float* x    = (const float*)d_in[0];
    const void*  ei   = d_in[1];
    const float* ew   = (const float*)d_in[2];
    const float* Wxz0 = (const float*)d_in[3];
    const float* Wxz1 = (const float*)d_in[4];
    const float* bxz  = (const float*)d_in[5];
    const float* bhz  = (const float*)d_in[8];
    const float* Wxh0 = (const float*)d_in[15];
    const float* Wxh1 = (const float*)d_in[16];
    const float* bxh  = (const float*)d_in[17];
    const float* bhh  = (const float*)d_in[20];
    const float* Wlin = (const float*)d_in[21];
    const float* blin = (const float*)d_in[22];
    float* out = (float*)d_out;

    int n = in_sizes[0] / 64;   // 50000
    int e = in_sizes[2];        // 800000

    static int s_attr_done = 0;
    if (!s_attr_done) {
        cudaFuncSetAttribute(k_fused, cudaFuncAttributeMaxDynamicSharedMemorySize, 98944);
        s_attr_done = 1;
    }

    int nbE = (e + 255) / 256;

    k_zero_edge1<<<NBZ + nbE, 256>>>(ei, ew, e, n);     // #1
    k_scan_edge2<<<NBZ + nbE, 256>>>(ei, ew, e, n);     // #2
    k_prop<<<(n * 32 + 255) / 256, 256>>>(x, n);        // #3
    k_fused<<<(n + TM - 1) / TM, 256, 98944>>>(         // #4  <- ncu window
        x, Wxz0, Wxz1, bxz, bhz, Wxh0, Wxh1, bxh, bhh, Wlin, blin, out, n);
}

// round 9
// speedup vs baseline: 1.3674x; 1.2934x over previous
#include <cuda_runtime.h>
#include <cuda_bf16.h>
#include <math.h>

// Problem constants: N=50000 nodes, E=800000 edges, F=64, HID=64, OUT=32
#define MAXN 50176      // 49*1024, divisible by 4
#define MAXE 800008     // +8 pad: prop prefetches one past segment end
#define NBZ 49          // zero/scan blocks (1024 elems each)

// ---------- device scratch (no allocations allowed) ----------
__device__ __align__(16) float g_deg[MAXN];
__device__ __align__(16) float g_dinv[MAXN];
__device__ __align__(16) int   g_count[MAXN];
__device__ __align__(16) int   g_cursor[MAXN];
__device__ __align__(16) int   g_offs[MAXN];
__device__ __align__(16) int   g_bpref[64];
__device__ __align__(16) int2  g_pair[MAXE];   // (src, bitcast(coef))
__device__ __align__(16) float g_px[MAXN * 64];
__device__ int g_is64;     // 1 if edge_index is int64, 0 if int32
__device__ int g_done_a;   // zero-phase completion counter (reset by k_fused)
__device__ int g_done_b;   // scan-phase completion counter (reset by k_fused)

__device__ __forceinline__ int load_idx(const void* ei, int pos) {
    if (g_is64) return (int)((const long long*)ei)[pos];
    return ((const int*)ei)[pos];
}
__device__ __forceinline__ int clampi(int v, int n) {
    return ((unsigned)v < (unsigned)n) ? v : 0;
}

// ---------- packed f32x2 helpers (FFMA2) ----------
__device__ __forceinline__ void ffma2(unsigned long long& d, unsigned long long a,
                                      unsigned long long b) {
    asm("fma.rn.f32x2 %0, %1, %2, %0;" : "+l"(d) : "l"(a), "l"(b));
}
__device__ __forceinline__ unsigned long long dupf(float f) {
    unsigned long long r;
    asm("mov.b64 %0, {%1, %1};" : "=l"(r) : "f"(f));
    return r;
}
__device__ __forceinline__ unsigned long long packf(float lo, float hi) {
    unsigned long long r;
    asm("mov.b64 %0, {%1, %2};" : "=l"(r) : "f"(lo), "f"(hi));
    return r;
}
__device__ __forceinline__ void unpackf(unsigned long long v, float& lo, float& hi) {
    asm("mov.b64 {%0, %1}, %2;" : "=f"(lo), "=f"(hi) : "l"(v));
}

// ---------- A: zero + dtype detect (blocks 0..48) | edge1 (blocks 49..) ----------
__global__ void k_zero_edge1(const void* __restrict__ ei, const float* __restrict__ ew,
                             int e, int n) {
    int bid = blockIdx.x, tid = threadIdx.x;
    if (bid < NBZ) {
        int i = bid * 256 + tid;          // int4 index, 1024 elems/block
        int4 z = make_int4(0, 0, 0, 0);
        reinterpret_cast<int4*>(g_deg)[i] = z;
        reinterpret_cast<int4*>(g_count)[i] = z;
        reinterpret_cast<int4*>(g_cursor)[i] = z;
        if (bid == 0) {
            if (tid < 64) g_bpref[tid] = 0;
            __shared__ int any;
            if (tid == 0) any = 0;
            __syncthreads();
            // int64 small nonneg values -> every odd 32-bit word is 0
            if (tid < 128 && ((const int*)ei)[2 * tid + 1] != 0) atomicOr(&any, 1);
            __syncthreads();
            if (tid == 0) g_is64 = (any == 0) ? 1 : 0;
        }
        __syncthreads();
        __threadfence();
        if (tid == 0) atomicAdd(&g_done_a, 1);
    } else {
        if (tid == 0) { while (atomicAdd(&g_done_a, 0) < NBZ) {} }
        __syncthreads();
        __threadfence();
        int i = (bid - NBZ) * 256 + tid;
        if (i < e) {
            int s = clampi(load_idx(ei, i), n);
            int d = clampi(load_idx(ei, e + i), n);
            atomicAdd(&g_deg[s], ew[i]);
            atomicAdd(&g_count[d], 1);
        }
    }
}

// ---------- B: dinv + scan (blocks 0..48) | edge2 bucket fill (blocks 49..) ----------
__global__ void k_scan_edge2(const void* __restrict__ ei, const float* __restrict__ ew,
                             int e, int n) {
    int bid = blockIdx.x, tid = threadIdx.x;
    if (bid < NBZ) {
        __shared__ int sh[256];
        __shared__ int s_total;
        int4 c4 = reinterpret_cast<const int4*>(g_count)[bid * 256 + tid];
        float4 d4 = reinterpret_cast<const float4*>(g_deg)[bid * 256 + tid];
        float4 dv;
        dv.x = (d4.x > 0.f) ? rsqrtf(d4.x) : 0.f;
        dv.y = (d4.y > 0.f) ? rsqrtf(d4.y) : 0.f;
        dv.z = (d4.z > 0.f) ? rsqrtf(d4.z) : 0.f;
        dv.w = (d4.w > 0.f) ? rsqrtf(d4.w) : 0.f;
        reinterpret_cast<float4*>(g_dinv)[bid * 256 + tid] = dv;
        int tsum = c4.x + c4.y + c4.z + c4.w;
        sh[tid] = tsum;
        __syncthreads();
        for (int d = 1; d < 256; d <<= 1) {
            int add = (tid >= d) ? sh[tid - d] : 0;
            __syncthreads();
            sh[tid] += add;
            __syncthreads();
        }
        int excl = sh[tid] - tsum;
        int4 o4;
        o4.x = excl;
        o4.y = excl + c4.x;
        o4.z = excl + c4.x + c4.y;
        o4.w = excl + c4.x + c4.y + c4.z;
        reinterpret_cast<int4*>(g_offs)[bid * 256 + tid] = o4;
        if (tid == 255) s_total = sh[255];
        __syncthreads();
        int b2 = bid + 1 + tid;
        if (tid < 64 && b2 < NBZ) atomicAdd(&g_bpref[b2], s_total);
        __threadfence();
        __syncthreads();
        if (tid == 0) atomicAdd(&g_done_b, 1);
    } else {
        if (tid == 0) { while (atomicAdd(&g_done_b, 0) < NBZ) {} }
        __syncthreads();
        __threadfence();
        int i = (bid - NBZ) * 256 + tid;
        if (i < e) {
            int s = clampi(load_idx(ei, i), n);
            int d = clampi(load_idx(ei, e + i), n);
            int pos = g_offs[d] + g_bpref[d >> 10] + atomicAdd(&g_cursor[d], 1);
            pos = clampi(pos, e);
            float c = -g_dinv[s] * ew[i] * g_dinv[d];
            g_pair[pos] = make_int2(s, __float_as_int(c));
        }
    }
}

// ---------- K3: propagation px[dst] = sum coef * x[src], one warp per dst ----------
__global__ void k_prop(const float* __restrict__ x, int n) {
    int gw = (blockIdx.x * blockDim.x + threadIdx.x) >> 5;
    int lane = threadIdx.x & 31;
    if (gw >= n) return;
    int start = g_offs[gw] + g_bpref[gw >> 10];
    int m = g_count[gw];
    float a0 = 0.f, a1 = 0.f;
    if (m > 0) {
        int2 sc = __ldg(&g_pair[start]);
        for (int j = 0; j < m; j++) {
            int2 nxt = __ldg(&g_pair[start + j + 1]);  // MAXE pad
            const float* xr = x + (size_t)sc.x * 64;
            float c = __int_as_float(sc.y);
            a0 = fmaf(c, __ldg(&xr[lane]), a0);
            a1 = fmaf(c, __ldg(&xr[lane + 32]), a1);
            sc = nxt;
        }
    }
    g_px[(size_t)gw * 64 + lane] = a0;
    g_px[(size_t)gw * 64 + 32 + lane] = a1;
}

// ---------- K4: fused [x|px]@Wzh -> gate -> @Wlin -> L2-normalize ----------
// TM=64 nodes/block, 256 threads, 8-node x 4-out register tile, f32x2 math.
#define TM 64
#define SP 148   // sIN row stride (floats): mult of 4, node rows hit distinct banks
__global__ __launch_bounds__(256, 2) void k_fused(
    const float* __restrict__ x,
    const float* __restrict__ Wxz0, const float* __restrict__ Wxz1,
    const float* __restrict__ bxz,  const float* __restrict__ bhz,
    const float* __restrict__ Wxh0, const float* __restrict__ Wxh1,
    const float* __restrict__ bxh,  const float* __restrict__ bhh,
    const float* __restrict__ Wlin, const float* __restrict__ blin,
    float* __restrict__ out, int n)
{
    extern __shared__ __align__(16) float sh[];
    float* sW   = sh;                 // 128*128 = 16384
    float* sWl  = sW + 16384;         // 64*32   = 2048
    float* sB   = sWl + 2048;         // 128
    float* sBl  = sB + 128;           // 32
    float* sIN  = sBl + 32;           // 64*SP   = 9472
    // total 28064 floats = 112256 bytes

    int tid = threadIdx.x;
    if (blockIdx.x == 0 && tid == 0) { g_done_a = 0; g_done_b = 0; }  // replay reset

    // weights/biases -> smem
    for (int idx = tid; idx < 16384; idx += 256) {
        int k = idx >> 7, o = idx & 127;
        float v;
        if (k < 64) v = (o < 64) ? Wxz0[k * 64 + o] : Wxh0[k * 64 + (o - 64)];
        else        v = (o < 64) ? Wxz1[(k - 64) * 64 + o] : Wxh1[(k - 64) * 64 + (o - 64)];
        sW[idx] = v;
    }
    for (int idx = tid; idx < 2048; idx += 256) sWl[idx] = Wlin[idx];
    if (tid < 128) sB[tid] = (tid < 64) ? (bxz[tid] + bhz[tid]) : (bxh[tid - 64] + bhh[tid - 64]);
    if (tid < 32) sBl[tid] = blin[tid];

    int node0 = blockIdx.x * TM;

    // input tile: sIN[r][0:64]=x, sIN[r][64:128]=px  (row stride SP)
    for (int idx = tid; idx < TM * 32; idx += 256) {
        int r = idx >> 5, c4 = idx & 31;
        int node = node0 + r;
        float4 v = make_float4(0.f, 0.f, 0.f, 0.f);
        if (node < n) {
            if (c4 < 16) v = reinterpret_cast<const float4*>(x)[(size_t)node * 16 + c4];
            else         v = reinterpret_cast<const float4*>(g_px)[(size_t)node * 16 + (c4 - 16)];
        }
        reinterpret_cast<float4*>(&sIN[r * SP])[c4] = v;
    }
    __syncthreads();

    // stage A GEMM: 64 nodes x 128 outputs, K=128, f32x2 packed
    int og = tid & 31;     // out group: outs og*4 .. og*4+3
    int ng = tid >> 5;     // node group: nodes ng*8 .. ng*8+7
    int ob = og * 4;
    unsigned long long acc[8][2];
    {
        unsigned long long b0 = packf(sB[ob], sB[ob + 1]);
        unsigned long long b1 = packf(sB[ob + 2], sB[ob + 3]);
#pragma unroll
        for (int i = 0; i < 8; i++) { acc[i][0] = b0; acc[i][1] = b1; }
    }
    const float* inp = sIN + ng * 8 * SP;
#pragma unroll 4
    for (int k = 0; k < 128; k += 2) {
        ulonglong2 wa = *reinterpret_cast<const ulonglong2*>(&sW[k * 128 + ob]);
        ulonglong2 wb = *reinterpret_cast<const ulonglong2*>(&sW[(k + 1) * 128 + ob]);
#pragma unroll
        for (int i = 0; i < 8; i++) {
            float2 in2 = *reinterpret_cast<const float2*>(&inp[i * SP + k]);
            unsigned long long p0 = dupf(in2.x);
            unsigned long long p1 = dupf(in2.y);
            ffma2(acc[i][0], p0, wa.x);
            ffma2(acc[i][1], p0, wa.y);
            ffma2(acc[i][0], p1, wb.x);
            ffma2(acc[i][1], p1, wb.y);
        }
    }
    __syncthreads();
    // writeback preacts into sIN (128 cols per row)
#pragma unroll
    for (int i = 0; i < 8; i++) {
        ulonglong2 v; v.x = acc[i][0]; v.y = acc[i][1];
        *reinterpret_cast<ulonglong2*>(&sIN[(ng * 8 + i) * SP + ob]) = v;
    }
    __syncthreads();

    // gate: U = (1 - sigmoid(z)) * tanh(h), written over z's slot (cols 0..63)
    for (int idx = tid; idx < TM * 64; idx += 256) {
        int r = idx >> 6, j = idx & 63;
        float zp = sIN[r * SP + j];
        float hp = sIN[r * SP + 64 + j];
        float z = 1.f / (1.f + __expf(-zp));
        sIN[r * SP + j] = (1.f - z) * tanhf(hp);
    }
    __syncthreads();

    // stage B: U(64x64) @ Wlin(64x32) + blin, f32x2, then row-normalize
    int node = tid >> 2;       // 0..63
    int q = tid & 3;           // out octet: outs q*8 .. q*8+7
    int ob2 = q * 8;
    unsigned long long a[4];
#pragma unroll
    for (int m2 = 0; m2 < 4; m2++) a[m2] = packf(sBl[ob2 + 2 * m2], sBl[ob2 + 2 * m2 + 1]);
#pragma unroll 8
    for (int k = 0; k < 64; k++) {
        unsigned long long up = dupf(sIN[node * SP + k]);
        ulonglong2 w0 = *reinterpret_cast<const ulonglong2*>(&sWl[k * 32 + ob2]);
        ulonglong2 w1 = *reinterpret_cast<const ulonglong2*>(&sWl[k * 32 + ob2 + 4]);
        ffma2(a[0], up, w0.x);
        ffma2(a[1], up, w0.y);
        ffma2(a[2], up, w1.x);
        ffma2(a[3], up, w1.y);
    }
    float o[8];
#pragma unroll
    for (int m2 = 0; m2 < 4; m2++) unpackf(a[m2], o[2 * m2], o[2 * m2 + 1]);
    float ss = 0.f;
#pragma unroll
    for (int m2 = 0; m2 < 8; m2++) ss = fmaf(o[m2], o[m2], ss);
    ss += __shfl_xor_sync(0xffffffffu, ss, 1);
    ss += __shfl_xor_sync(0xffffffffu, ss, 2);
    float scale = 1.f / fmaxf(sqrtf(ss), 1e-12f);
    int gnode = node0 + node;
    if (gnode < n) {
        float4 v0 = make_float4(o[0] * scale, o[1] * scale, o[2] * scale, o[3] * scale);
        float4 v1 = make_float4(o[4] * scale, o[5] * scale, o[6] * scale, o[7] * scale);
        reinterpret_cast<float4*>(out)[(size_t)gnode * 8 + q * 2] = v0;
        reinterpret_cast<float4*>(out)[(size_t)gnode * 8 + q * 2 + 1] = v1;
    }
}

extern "C" void kernel_launch(void* const* d_in, const int* in_sizes, int n_in,
                              void* d_out, int out_size) {
    const float* x    = (const float*)d_in[0];
    const void*  ei   = d_in[1];
    const float* ew   = (const float*)d_in[2];
    const float* Wxz0 = (const float*)d_in[3];
    const float* Wxz1 = (const float*)d_in[4];
    const float* bxz  = (const float*)d_in[5];
    const float* bhz  = (const float*)d_in[8];
    const float* Wxh0 = (const float*)d_in[15];
    const float* Wxh1 = (const float*)d_in[16];
    const float* bxh  = (const float*)d_in[17];
    const float* bhh  = (const float*)d_in[20];
    const float* Wlin = (const float*)d_in[21];
    const float* blin = (const float*)d_in[22];
    float* out = (float*)d_out;

    int n = in_sizes[0] / 64;   // 50000
    int e = in_sizes[2];        // 800000

    static int s_attr_done = 0;
    if (!s_attr_done) {
        cudaFuncSetAttribute(k_fused, cudaFuncAttributeMaxDynamicSharedMemorySize, 112256);
        s_attr_done = 1;
    }

    int nbE = (e + 255) / 256;

    k_zero_edge1<<<NBZ + nbE, 256>>>(ei, ew, e, n);     // #1
    k_scan_edge2<<<NBZ + nbE, 256>>>(ei, ew, e, n);     // #2
    k_prop<<<(n * 32 + 255) / 256, 256>>>(x, n);        // #3
    k_fused<<<(n + TM - 1) / TM, 256, 112256>>>(        // #4  <- ncu window
        x, Wxz0, Wxz1, bxz, bhz, Wxh0, Wxh1, bxh, bhh, Wlin, blin, out, n);
}